// round 6
// baseline (speedup 1.0000x reference)
#include <cuda_runtime.h>
#include <cuda_fp16.h>

#define D 64
#define NU_MAX 100001
#define NI_MAX 200001
#define NMAX (NU_MAX + NI_MAX)
#define PMAX 3200000
#define SCAN_BLK 1024

// Scratch (.bss, no allocation).
__device__ float g_h1[(size_t)NMAX * D];       // layer-1 output
__device__ float g_h2[(size_t)NMAX * D];       // layer-2 output
__device__ int2  g_edge[2 * PMAX];             // packed {col, val_bits}; [0,P)=user CSR, [P,2P)=item CSC
__device__ int   g_u_ptr[NU_MAX + 2];
__device__ int   g_i_ptr[NI_MAX + 2];
__device__ int   g_i_work[NI_MAX + 2];
__device__ int   g_cnt[NI_MAX + 2];
__device__ int   g_bsums[512];

// ---------------------------------------------------------------------------
// prep (fused): [0,P)            -> count item degrees + pack user-block edges
//               [P, P+n_users+1) -> u_ptr binary search over sorted row[0:P]
//               [0, n_cnt)       -> zero counters first? (separate range below)
// zeroing cnt must happen before counting -> do zeroing in its own range and
// order via a separate tiny kernel? Instead: zero cnt with thread range
// [P+n_users+1, P+n_users+1+n_cnt) is WRONG (no intra-grid ordering).
// So counters are zeroed by a dedicated leading kernel (tiny, 200k threads).
// ---------------------------------------------------------------------------
__global__ void zero_cnt_kernel(int* __restrict__ cnt, int n_cnt) {
    int i = blockIdx.x * blockDim.x + threadIdx.x;
    if (i < n_cnt) cnt[i] = 0;
}

__global__ void prep_kernel(const int* __restrict__ row,
                            const int* __restrict__ col,
                            const float* __restrict__ vals, int P,
                            int* __restrict__ cnt,
                            int2* __restrict__ edge,
                            int* __restrict__ uptr,
                            int n_users) {
    int t = blockIdx.x * blockDim.x + threadIdx.x;
    if (t < P) {
        int c = col[t];
        atomicAdd(&cnt[c - n_users], 1);
        edge[t] = make_int2(c, __float_as_int(vals[t]));
    } else {
        int r = t - P;
        if (r > n_users) return;
        int lo = 0, hi = P;
        while (lo < hi) {
            int mid = (lo + hi) >> 1;
            if (row[mid] < r) lo = mid + 1; else hi = mid;
        }
        uptr[r] = lo;
    }
}

// ---------------------------------------------------------------------------
// exclusive scan of cnt[0:n] -> i_ptr (+P offset into packed edge array)
// ---------------------------------------------------------------------------
__global__ void scan1_kernel(const int* __restrict__ cnt, int* __restrict__ ptr,
                             int* __restrict__ bsums, int n) {
    __shared__ int sh[SCAN_BLK];
    int i = blockIdx.x * SCAN_BLK + threadIdx.x;
    int v = (i < n) ? cnt[i] : 0;
    sh[threadIdx.x] = v;
    __syncthreads();
    for (int off = 1; off < SCAN_BLK; off <<= 1) {
        int t = 0;
        if ((int)threadIdx.x >= off) t = sh[threadIdx.x - off];
        __syncthreads();
        sh[threadIdx.x] += t;
        __syncthreads();
    }
    if (i < n) ptr[i] = sh[threadIdx.x] - v;   // exclusive
    if (threadIdx.x == SCAN_BLK - 1) bsums[blockIdx.x] = sh[SCAN_BLK - 1];
}

__global__ void scan2_kernel(int* __restrict__ bsums, int nb) {
    __shared__ int sh[512];
    int v = ((int)threadIdx.x < nb) ? bsums[threadIdx.x] : 0;
    sh[threadIdx.x] = v;
    __syncthreads();
    for (int off = 1; off < 512; off <<= 1) {
        int t = 0;
        if ((int)threadIdx.x >= off) t = sh[threadIdx.x - off];
        __syncthreads();
        sh[threadIdx.x] += t;
        __syncthreads();
    }
    if ((int)threadIdx.x < nb) bsums[threadIdx.x] = sh[threadIdx.x] - v;  // exclusive
}

__global__ void scan3_kernel(int* __restrict__ ptr, int* __restrict__ work,
                             const int* __restrict__ bsums, int n, int offset) {
    int i = blockIdx.x * blockDim.x + threadIdx.x;
    if (i >= n) return;
    int p = ptr[i] + bsums[i >> 10] + offset;
    ptr[i] = p;
    work[i] = p;
}

// ---------------------------------------------------------------------------
// scatter transpose (item CSC) into the packed edge array, single 8B store
// ---------------------------------------------------------------------------
__global__ void scatter_kernel(const int* __restrict__ row,
                               const int* __restrict__ col,
                               const float* __restrict__ vals, int P,
                               int* __restrict__ iwork,
                               int2* __restrict__ edge, int n_users) {
    int e = blockIdx.x * blockDim.x + threadIdx.x;
    if (e >= P) return;
    int it = col[e] - n_users;
    int pos = atomicAdd(&iwork[it], 1);   // already offset by P
    edge[pos] = make_int2(row[e], __float_as_int(vals[e]));
}

// ---------------------------------------------------------------------------
// Warp-per-row SpMM (fp32): acc = sum v * x[c]; lane owns one float2 (8B) of
// the 256B feature row. Gather base selected per edge: c < n_users -> xu,
// else xi (xi is pre-offset so xi + c*32 lands on item row c-n_users).
// For hidden layers xu == xi == buffer, select is a no-op.
// ---------------------------------------------------------------------------
#define EDGE_FMA(c_, vbits_)  {                                              \
    float v_ = __int_as_float(vbits_);                                       \
    const float2* b_ = ((c_) < n_users) ? xu : xi;                           \
    float2 f_ = b_[(size_t)(c_) * 32 + lane];                                \
    a0 = fmaf(v_, f_.x, a0); a1 = fmaf(v_, f_.y, a1); }

__device__ __forceinline__ void row_accum(const float2* __restrict__ xu,
                                          const float2* __restrict__ xi,
                                          const int2* __restrict__ edge,
                                          int s, int e, int lane, int n_users,
                                          float& a0, float& a1) {
    int ei = s;
    if (ei < e && (ei & 1)) {            // align to 16B for int4 loads
        int2 p = edge[ei];
        EDGE_FMA(p.x, p.y)
        ei++;
    }
    for (; ei + 8 <= e; ei += 8) {
        int4 p0 = *reinterpret_cast<const int4*>(edge + ei);
        int4 p1 = *reinterpret_cast<const int4*>(edge + ei + 2);
        int4 p2 = *reinterpret_cast<const int4*>(edge + ei + 4);
        int4 p3 = *reinterpret_cast<const int4*>(edge + ei + 6);
        EDGE_FMA(p0.x, p0.y) EDGE_FMA(p0.z, p0.w)
        EDGE_FMA(p1.x, p1.y) EDGE_FMA(p1.z, p1.w)
        EDGE_FMA(p2.x, p2.y) EDGE_FMA(p2.z, p2.w)
        EDGE_FMA(p3.x, p3.y) EDGE_FMA(p3.z, p3.w)
    }
    for (; ei < e; ei++) {
        int2 p = edge[ei];
        EDGE_FMA(p.x, p.y)
    }
}

__global__ void spmm_kernel(const float2* __restrict__ xu,
                            const float2* __restrict__ xi,   // pre-offset for item rows
                            float2* __restrict__ y,
                            const int2* __restrict__ edge,
                            const int* __restrict__ uptr,
                            const int* __restrict__ iptr,
                            int n_users, int n_total) {
    int w = (blockIdx.x * blockDim.x + threadIdx.x) >> 5;
    int lane = threadIdx.x & 31;
    if (w >= n_total) return;
    int s, e;
    if (w < n_users) { s = uptr[w]; e = uptr[w + 1]; }
    else { int ii = w - n_users; s = iptr[ii]; e = iptr[ii + 1]; }

    float a0 = 0.f, a1 = 0.f;
    row_accum(xu, xi, edge, s, e, lane, n_users, a0, a1);
    y[(size_t)w * 32 + lane] = make_float2(a0, a1);
}

// last layer fused with the epilogue: out = (x0 + h1 + h2 + acc) * 0.25
__global__ void spmm_final_kernel(const float2* __restrict__ x,   // h2 (both blocks)
                                  const float2* __restrict__ ue,
                                  const float2* __restrict__ ie,
                                  const float2* __restrict__ h1,
                                  float2* __restrict__ out,
                                  const int2* __restrict__ edge,
                                  const int* __restrict__ uptr,
                                  const int* __restrict__ iptr,
                                  int n_users, int n_total) {
    int w = (blockIdx.x * blockDim.x + threadIdx.x) >> 5;
    int lane = threadIdx.x & 31;
    if (w >= n_total) return;
    int s, e;
    if (w < n_users) { s = uptr[w]; e = uptr[w + 1]; }
    else { int ii = w - n_users; s = iptr[ii]; e = iptr[ii + 1]; }

    float a0 = 0.f, a1 = 0.f;
    {   // hidden layers gather from a single contiguous buffer
        const float2* xu = x;
        const float2* xi = x;
        row_accum(xu, xi, edge, s, e, lane, n_users, a0, a1);
    }

    size_t o = (size_t)w * 32 + lane;
    float2 x0 = (w < n_users) ? ue[o] : ie[o - (size_t)n_users * 32];
    float2 f1 = h1[o];
    float2 f2 = x[o];
    float2 r;
    r.x = (x0.x + f1.x + f2.x + a0) * 0.25f;
    r.y = (x0.y + f1.y + f2.y + a1) * 0.25f;
    out[o] = r;
}

extern "C" void kernel_launch(void* const* d_in, const int* in_sizes, int n_in,
                              void* d_out, int out_size) {
    const float* user_emb = (const float*)d_in[0];
    const float* item_emb = (const float*)d_in[1];
    const int*   row      = (const int*)d_in[2];
    const int*   col      = (const int*)d_in[3];
    const float* vals     = (const float*)d_in[4];

    const int n_users = in_sizes[0] / D;
    const int n_items = in_sizes[1] / D;
    const int n_total = n_users + n_items;
    const int E       = in_sizes[2];
    const int P       = E / 2;          // first half = user rows (sorted)

    float* out = (float*)d_out;

    float *h1, *h2;
    int *u_ptr, *i_ptr, *i_work, *cnt, *bsums;
    int2 *edge;
    cudaGetSymbolAddress((void**)&h1, g_h1);
    cudaGetSymbolAddress((void**)&h2, g_h2);
    cudaGetSymbolAddress((void**)&edge, g_edge);
    cudaGetSymbolAddress((void**)&u_ptr, g_u_ptr);
    cudaGetSymbolAddress((void**)&i_ptr, g_i_ptr);
    cudaGetSymbolAddress((void**)&i_work, g_i_work);
    cudaGetSymbolAddress((void**)&cnt, g_cnt);
    cudaGetSymbolAddress((void**)&bsums, g_bsums);

    const int TB = 256;
    const int n_cnt = n_items + 1;

    // item-row gather base, pre-offset so that (xi + c*32) hits item row c-n_users
    const float2* ue2 = (const float2*)user_emb;
    const float2* ie2 = (const float2*)item_emb;
    const float2* ie2_off = ie2 - (size_t)n_users * 32;

    // 0. zero item counters
    zero_cnt_kernel<<<(n_cnt + TB - 1) / TB, TB>>>(cnt, n_cnt);

    // 1. fused: pack user edges + count item degrees + u_ptr binary search
    int prep_threads = P + n_users + 1;
    prep_kernel<<<(prep_threads + TB - 1) / TB, TB>>>(row, col, vals, P,
                                                      cnt, edge, u_ptr, n_users);

    // 2-4. exclusive scan -> i_ptr (offset by P into packed edge array)
    int n_scan = n_cnt;
    int nb = (n_scan + SCAN_BLK - 1) / SCAN_BLK;
    scan1_kernel<<<nb, SCAN_BLK>>>(cnt, i_ptr, bsums, n_scan);
    scan2_kernel<<<1, 512>>>(bsums, nb);
    scan3_kernel<<<(n_scan + TB - 1) / TB, TB>>>(i_ptr, i_work, bsums, n_scan, P);

    // 5. scatter transpose (item CSC), packed 8B stores   [launch idx 5... next is spmm]
    scatter_kernel<<<(P + TB - 1) / TB, TB>>>(row, col, vals, P, i_work, edge, n_users);

    // 6-8. three SpMM layers (warp-per-row, atomic-free, fp32)
    int spmm_blocks = (n_total * 32 + TB - 1) / TB;
    // layer 0: gather straight from the input embeddings (no init copy)
    spmm_kernel<<<spmm_blocks, TB>>>(ue2, ie2_off, (float2*)h1,
                                     edge, u_ptr, i_ptr, n_users, n_total);
    // layer 1: h1 -> h2
    spmm_kernel<<<spmm_blocks, TB>>>((const float2*)h1, (const float2*)h1, (float2*)h2,
                                     edge, u_ptr, i_ptr, n_users, n_total);
    // layer 2 (final, fused epilogue)
    spmm_final_kernel<<<spmm_blocks, TB>>>((const float2*)h2, ue2, ie2,
                                           (const float2*)h1, (float2*)out,
                                           edge, u_ptr, i_ptr, n_users, n_total);
}

// round 8
// speedup vs baseline: 1.7048x; 1.7048x over previous
#include <cuda_runtime.h>
#include <cuda_fp16.h>

#define D 64
#define NU_MAX 100001
#define NI_MAX 200001
#define NMAX (NU_MAX + NI_MAX)
#define PMAX 3200000
#define SCAN_BLK 1024

__device__ __forceinline__ __half2 u2h2(unsigned u) {
    __half2 h; *reinterpret_cast<unsigned*>(&h) = u; return h;
}
__device__ __forceinline__ unsigned h22u(__half2 h) {
    return *reinterpret_cast<unsigned*>(&h);
}

// Scratch (.bss, no allocation). fp16 feature rows: 64 halves = 128B.
__device__ __half g_x0[(size_t)NMAX * D];
__device__ __half g_h1[(size_t)NMAX * D];
__device__ __half g_h2[(size_t)NMAX * D];
__device__ int2   g_edge[2 * PMAX];       // {col, val_bits}; [0,P)=user CSR, [P,2P)=item CSC
__device__ int    g_u_ptr[NU_MAX + 2];
__device__ int    g_i_ptr[NI_MAX + 2];
__device__ int    g_i_work[NI_MAX + 2];
__device__ int    g_cnt[NI_MAX + 2];
__device__ int    g_bsums[512];

// ---------------------------------------------------------------------------
// init: g_x0 = half(concat(ue, ie)); zero item counters.
// thread i produces one uint4 (8 halves) from two float4 (8 floats).
// ---------------------------------------------------------------------------
__global__ void init_kernel(const float4* __restrict__ ue,
                            const float4* __restrict__ ie,
                            uint4* __restrict__ x0,
                            int* __restrict__ cnt,
                            int n_user_u4, int n_total_u4, int n_cnt) {
    int i = blockIdx.x * blockDim.x + threadIdx.x;
    if (i < n_cnt) cnt[i] = 0;
    if (i >= n_total_u4) return;
    const float4* src = (i < n_user_u4) ? (ue + (size_t)i * 2)
                                        : (ie + (size_t)(i - n_user_u4) * 2);
    float4 f0 = src[0];
    float4 f1 = src[1];
    uint4 o;
    o.x = h22u(__floats2half2_rn(f0.x, f0.y));
    o.y = h22u(__floats2half2_rn(f0.z, f0.w));
    o.z = h22u(__floats2half2_rn(f1.x, f1.y));
    o.w = h22u(__floats2half2_rn(f1.z, f1.w));
    x0[i] = o;
}

// ---------------------------------------------------------------------------
// u_ptr[r] = lower_bound(row[0:P], r)
// ---------------------------------------------------------------------------
__global__ void build_uptr_kernel(const int* __restrict__ row, int P,
                                  int* __restrict__ uptr, int n_users) {
    int r = blockIdx.x * blockDim.x + threadIdx.x;
    if (r > n_users) return;
    int lo = 0, hi = P;
    while (lo < hi) {
        int mid = (lo + hi) >> 1;
        if (row[mid] < r) lo = mid + 1; else hi = mid;
    }
    uptr[r] = lo;
}

// ---------------------------------------------------------------------------
// count item degrees + pack user-block edges
// ---------------------------------------------------------------------------
__global__ void count_pack_kernel(const int* __restrict__ col,
                                  const float* __restrict__ vals, int P,
                                  int* __restrict__ cnt,
                                  int2* __restrict__ edge, int n_users) {
    int e = blockIdx.x * blockDim.x + threadIdx.x;
    if (e >= P) return;
    int c = col[e];
    atomicAdd(&cnt[c - n_users], 1);
    edge[e] = make_int2(c, __float_as_int(vals[e]));
}

// ---------------------------------------------------------------------------
// exclusive scan -> i_ptr (+P offset)
// ---------------------------------------------------------------------------
__global__ void scan1_kernel(const int* __restrict__ cnt, int* __restrict__ ptr,
                             int* __restrict__ bsums, int n) {
    __shared__ int sh[SCAN_BLK];
    int i = blockIdx.x * SCAN_BLK + threadIdx.x;
    int v = (i < n) ? cnt[i] : 0;
    sh[threadIdx.x] = v;
    __syncthreads();
    for (int off = 1; off < SCAN_BLK; off <<= 1) {
        int t = 0;
        if ((int)threadIdx.x >= off) t = sh[threadIdx.x - off];
        __syncthreads();
        sh[threadIdx.x] += t;
        __syncthreads();
    }
    if (i < n) ptr[i] = sh[threadIdx.x] - v;
    if (threadIdx.x == SCAN_BLK - 1) bsums[blockIdx.x] = sh[SCAN_BLK - 1];
}

__global__ void scan2_kernel(int* __restrict__ bsums, int nb) {
    __shared__ int sh[512];
    int v = ((int)threadIdx.x < nb) ? bsums[threadIdx.x] : 0;
    sh[threadIdx.x] = v;
    __syncthreads();
    for (int off = 1; off < 512; off <<= 1) {
        int t = 0;
        if ((int)threadIdx.x >= off) t = sh[threadIdx.x - off];
        __syncthreads();
        sh[threadIdx.x] += t;
        __syncthreads();
    }
    if ((int)threadIdx.x < nb) bsums[threadIdx.x] = sh[threadIdx.x] - v;
}

__global__ void scan3_kernel(int* __restrict__ ptr, int* __restrict__ work,
                             const int* __restrict__ bsums, int n, int offset) {
    int i = blockIdx.x * blockDim.x + threadIdx.x;
    if (i >= n) return;
    int p = ptr[i] + bsums[i >> 10] + offset;
    ptr[i] = p;
    work[i] = p;
}

// ---------------------------------------------------------------------------
// scatter transpose (item CSC), single 8B store
// ---------------------------------------------------------------------------
__global__ void scatter_kernel(const int* __restrict__ row,
                               const int* __restrict__ col,
                               const float* __restrict__ vals, int P,
                               int* __restrict__ iwork,
                               int2* __restrict__ edge, int n_users) {
    int e = blockIdx.x * blockDim.x + threadIdx.x;
    if (e >= P) return;
    int it = col[e] - n_users;
    int pos = atomicAdd(&iwork[it], 1);   // already offset by P
    edge[pos] = make_int2(row[e], __float_as_int(vals[e]));
}

// ---------------------------------------------------------------------------
// SpMM, 8 lanes per row (4 rows per warp), fp16 gather via LDG.128
// (8 lanes x 16B = 128B row -> one warp gather instr serves 4 edges),
// fp32 accumulation in 8 registers per lane.
// ---------------------------------------------------------------------------
#define EDGE_FMA_H(c_, vbits_)  {                                            \
    float v_ = __int_as_float(vbits_);                                       \
    uint4 u_ = x[(size_t)(c_) * 8 + lane];                                   \
    float2 f0_ = __half22float2(u2h2(u_.x));                                 \
    float2 f1_ = __half22float2(u2h2(u_.y));                                 \
    float2 f2_ = __half22float2(u2h2(u_.z));                                 \
    float2 f3_ = __half22float2(u2h2(u_.w));                                 \
    a0 = fmaf(v_, f0_.x, a0); a1 = fmaf(v_, f0_.y, a1);                      \
    a2 = fmaf(v_, f1_.x, a2); a3 = fmaf(v_, f1_.y, a3);                      \
    a4 = fmaf(v_, f2_.x, a4); a5 = fmaf(v_, f2_.y, a5);                      \
    a6 = fmaf(v_, f3_.x, a6); a7 = fmaf(v_, f3_.y, a7); }

__device__ __forceinline__ void row_accum(const uint4* __restrict__ x,
                                          const int2* __restrict__ edge,
                                          int s, int e, int lane,
                                          float& a0, float& a1, float& a2, float& a3,
                                          float& a4, float& a5, float& a6, float& a7) {
    int ei = s;
    if (ei < e && (ei & 1)) {
        int2 p = edge[ei];
        EDGE_FMA_H(p.x, p.y)
        ei++;
    }
    for (; ei + 8 <= e; ei += 8) {
        int4 p0 = *reinterpret_cast<const int4*>(edge + ei);
        int4 p1 = *reinterpret_cast<const int4*>(edge + ei + 2);
        int4 p2 = *reinterpret_cast<const int4*>(edge + ei + 4);
        int4 p3 = *reinterpret_cast<const int4*>(edge + ei + 6);
        EDGE_FMA_H(p0.x, p0.y) EDGE_FMA_H(p0.z, p0.w)
        EDGE_FMA_H(p1.x, p1.y) EDGE_FMA_H(p1.z, p1.w)
        EDGE_FMA_H(p2.x, p2.y) EDGE_FMA_H(p2.z, p2.w)
        EDGE_FMA_H(p3.x, p3.y) EDGE_FMA_H(p3.z, p3.w)
    }
    for (; ei < e; ei++) {
        int2 p = edge[ei];
        EDGE_FMA_H(p.x, p.y)
    }
}

__global__ void spmm_kernel(const uint4* __restrict__ x,
                            uint4* __restrict__ y,
                            const int2* __restrict__ edge,
                            const int* __restrict__ uptr,
                            const int* __restrict__ iptr,
                            int n_users, int n_total) {
    int g = (blockIdx.x * blockDim.x + threadIdx.x) >> 3;   // 8 lanes per row
    int lane = threadIdx.x & 7;
    if (g >= n_total) return;
    int s, e;
    if (g < n_users) { s = uptr[g]; e = uptr[g + 1]; }
    else { int ii = g - n_users; s = iptr[ii]; e = iptr[ii + 1]; }

    float a0 = 0.f, a1 = 0.f, a2 = 0.f, a3 = 0.f,
          a4 = 0.f, a5 = 0.f, a6 = 0.f, a7 = 0.f;
    row_accum(x, edge, s, e, lane, a0, a1, a2, a3, a4, a5, a6, a7);

    uint4 o;
    o.x = h22u(__floats2half2_rn(a0, a1));
    o.y = h22u(__floats2half2_rn(a2, a3));
    o.z = h22u(__floats2half2_rn(a4, a5));
    o.w = h22u(__floats2half2_rn(a6, a7));
    y[(size_t)g * 8 + lane] = o;
}

// last layer + epilogue: out = (x0_f32 + h1 + h2 + acc) * 0.25  (fp32 out)
__global__ void spmm_final_kernel(const uint4* __restrict__ x,   // h2
                                  const float4* __restrict__ ue,
                                  const float4* __restrict__ ie,
                                  const uint4* __restrict__ h1,
                                  float4* __restrict__ out,
                                  const int2* __restrict__ edge,
                                  const int* __restrict__ uptr,
                                  const int* __restrict__ iptr,
                                  int n_users, int n_total) {
    int g = (blockIdx.x * blockDim.x + threadIdx.x) >> 3;
    int lane = threadIdx.x & 7;
    if (g >= n_total) return;
    int s, e;
    if (g < n_users) { s = uptr[g]; e = uptr[g + 1]; }
    else { int ii = g - n_users; s = iptr[ii]; e = iptr[ii + 1]; }

    float a0 = 0.f, a1 = 0.f, a2 = 0.f, a3 = 0.f,
          a4 = 0.f, a5 = 0.f, a6 = 0.f, a7 = 0.f;
    row_accum(x, edge, s, e, lane, a0, a1, a2, a3, a4, a5, a6, a7);

    size_t hoff = (size_t)g * 8 + lane;       // uint4 index (8 halves)
    uint4 u1 = h1[hoff];
    uint4 u2 = x[hoff];
    float2 b0 = __half22float2(u2h2(u1.x));
    float2 b1 = __half22float2(u2h2(u1.y));
    float2 b2 = __half22float2(u2h2(u1.z));
    float2 b3 = __half22float2(u2h2(u1.w));
    float2 c0 = __half22float2(u2h2(u2.x));
    float2 c1 = __half22float2(u2h2(u2.y));
    float2 c2 = __half22float2(u2h2(u2.z));
    float2 c3 = __half22float2(u2h2(u2.w));

    size_t foff = (size_t)g * 16 + lane * 2;  // float4 index (8 floats)
    const float4* x0p = (g < n_users) ? (ue + foff)
                                      : (ie + (foff - (size_t)n_users * 16));
    float4 x00 = x0p[0];
    float4 x01 = x0p[1];

    float4 r0, r1;
    r0.x = (x00.x + b0.x + c0.x + a0) * 0.25f;
    r0.y = (x00.y + b0.y + c0.y + a1) * 0.25f;
    r0.z = (x00.z + b1.x + c1.x + a2) * 0.25f;
    r0.w = (x00.w + b1.y + c1.y + a3) * 0.25f;
    r1.x = (x01.x + b2.x + c2.x + a4) * 0.25f;
    r1.y = (x01.y + b2.y + c2.y + a5) * 0.25f;
    r1.z = (x01.z + b3.x + c3.x + a6) * 0.25f;
    r1.w = (x01.w + b3.y + c3.y + a7) * 0.25f;
    out[foff] = r0;
    out[foff + 1] = r1;
}

extern "C" void kernel_launch(void* const* d_in, const int* in_sizes, int n_in,
                              void* d_out, int out_size) {
    const float* user_emb = (const float*)d_in[0];
    const float* item_emb = (const float*)d_in[1];
    const int*   row      = (const int*)d_in[2];
    const int*   col      = (const int*)d_in[3];
    const float* vals     = (const float*)d_in[4];

    const int n_users = in_sizes[0] / D;
    const int n_items = in_sizes[1] / D;
    const int n_total = n_users + n_items;
    const int E       = in_sizes[2];
    const int P       = E / 2;

    float* out = (float*)d_out;

    __half *x0h, *h1, *h2;
    int *u_ptr, *i_ptr, *i_work, *cnt, *bsums;
    int2 *edge;
    cudaGetSymbolAddress((void**)&x0h, g_x0);
    cudaGetSymbolAddress((void**)&h1, g_h1);
    cudaGetSymbolAddress((void**)&h2, g_h2);
    cudaGetSymbolAddress((void**)&edge, g_edge);
    cudaGetSymbolAddress((void**)&u_ptr, g_u_ptr);
    cudaGetSymbolAddress((void**)&i_ptr, g_i_ptr);
    cudaGetSymbolAddress((void**)&i_work, g_i_work);
    cudaGetSymbolAddress((void**)&cnt, g_cnt);
    cudaGetSymbolAddress((void**)&bsums, g_bsums);

    const int TB = 256;
    const int n_u4 = n_total * 8;          // uint4 units (8 halves each)
    const int n_user_u4 = n_users * 8;
    const int n_cnt = n_items + 1;

    // 1. init: x0h = half(x0); zero item counters
    init_kernel<<<(n_u4 + TB - 1) / TB, TB>>>(
        (const float4*)user_emb, (const float4*)item_emb,
        (uint4*)x0h, cnt, n_user_u4, n_u4, n_cnt);

    // 2. user CSR pointers
    build_uptr_kernel<<<(n_users + 1 + TB - 1) / TB, TB>>>(row, P, u_ptr, n_users);

    // 3. item degrees + pack user edges
    count_pack_kernel<<<(P + TB - 1) / TB, TB>>>(col, vals, P, cnt, edge, n_users);

    // 4. exclusive scan -> i_ptr
    int n_scan = n_cnt;
    int nb = (n_scan + SCAN_BLK - 1) / SCAN_BLK;
    scan1_kernel<<<nb, SCAN_BLK>>>(cnt, i_ptr, bsums, n_scan);
    scan2_kernel<<<1, 512>>>(bsums, nb);
    scan3_kernel<<<(n_scan + TB - 1) / TB, TB>>>(i_ptr, i_work, bsums, n_scan, P);

    // 5. scatter transpose
    scatter_kernel<<<(P + TB - 1) / TB, TB>>>(row, col, vals, P, i_work, edge, n_users);

    // 6-8. three SpMM layers (8 lanes/row: 4 edges per warp gather instr)
    int spmm_blocks = (n_total * 8 + TB - 1) / TB;
    spmm_kernel<<<spmm_blocks, TB>>>((const uint4*)x0h, (uint4*)h1,
                                     edge, u_ptr, i_ptr, n_users, n_total);
    spmm_kernel<<<spmm_blocks, TB>>>((const uint4*)h1, (uint4*)h2,
                                     edge, u_ptr, i_ptr, n_users, n_total);
    spmm_final_kernel<<<spmm_blocks, TB>>>((const uint4*)h2,
                                           (const float4*)user_emb, (const float4*)item_emb,
                                           (const uint4*)h1, (float4*)out,
                                           edge, u_ptr, i_ptr, n_users, n_total);
}